// round 15
// baseline (speedup 1.0000x reference)
#include <cuda.h>
#include <cuda_runtime.h>
#include <cuda_fp16.h>
#include <math.h>
#include <stdint.h>

// ---------------------------------------------------------------------------
// Problem constants
// ---------------------------------------------------------------------------
#define NN      8192
#define MREAL   101
#define MP      128
#define NCOLS   120                  // computed columns (15 x 8), >= MREAL
#define PITER   30
#define KSPLIT  4
#define KCHUNK  (NN / KSPLIT)        // 2048
#define KT      64                   // k per pipeline stage
#define KITERS  (KCHUNK / KT)        // 32
#define NSTG    4
#define ROWB    256
#define NTHR    384
#define NCTA    128                  // 32 rowblocks x KSPLIT, 1 CTA/SM
#define A_B     (ROWB * KT * 2)      // 32768 B: A tile (256 rows x 64 k fp16)
#define B_TX    (NCOLS * KT * 2)     // 15360 B actually transferred
#define B_SP    (128 * KT * 2)       // 16384 B reserved (ldsm overread pad)
#define STAGE_SP (A_B + B_SP)        // 49152 B
#define SMEM_DYN (1024 + NSTG * STAGE_SP)   // 197632 B

// ---------------------------------------------------------------------------
// Scratch (static device globals; no allocation allowed)
// ---------------------------------------------------------------------------
__device__ __half g_Khi16[(size_t)NN * NN];     // 128 MB: fp16-rounded K
__device__ __half g_Ph16[(size_t)MP * NN];      // scaled fp16 P, col-major
__device__ float  g_R[(size_t)MP * NN];
__device__ float  g_X[NN];
__device__ float  g_Vpart[(size_t)KSPLIT * MP * NN];  // 16 MB
__device__ float  g_alpha[PITER * MP];
__device__ float  g_beta[PITER * MP];
__device__ float  g_logdet;

// grid barrier state (self-resetting; g_gen monotonic across graph replays)
__device__ unsigned g_cnt = 0;
__device__ volatile unsigned g_gen = 0;

// ---------------------------------------------------------------------------
// PTX helpers (family-portable: ldmatrix / mma.sync / TMA / mbarrier)
// ---------------------------------------------------------------------------
__device__ __forceinline__ uint32_t smem_u32(const void* p) {
    uint32_t a;
    asm("{ .reg .u64 t; cvta.to.shared.u64 t, %1; cvt.u32.u64 %0, t; }"
        : "=r"(a) : "l"(p));
    return a;
}

__device__ __forceinline__ void ldsm_x4(uint32_t (&r)[4], uint32_t addr) {
    asm volatile("ldmatrix.sync.aligned.m8n8.x4.shared.b16 {%0,%1,%2,%3}, [%4];"
        : "=r"(r[0]), "=r"(r[1]), "=r"(r[2]), "=r"(r[3]) : "r"(addr));
}

__device__ __forceinline__ void mma16816(float (&d)[4], const uint32_t (&a)[4],
                                         uint32_t b0, uint32_t b1) {
    asm volatile("mma.sync.aligned.m16n8k16.row.col.f32.f16.f16.f32 "
        "{%0,%1,%2,%3}, {%4,%5,%6,%7}, {%8,%9}, {%0,%1,%2,%3};"
        : "+f"(d[0]), "+f"(d[1]), "+f"(d[2]), "+f"(d[3])
        : "r"(a[0]), "r"(a[1]), "r"(a[2]), "r"(a[3]), "r"(b0), "r"(b1));
}

#define MBAR_INIT(addr, cnt) \
    asm volatile("mbarrier.init.shared.b64 [%0], %1;" :: "r"(addr), "r"(cnt) : "memory")
#define MBAR_ARRIVE(addr) \
    asm volatile("mbarrier.arrive.shared.b64 _, [%0];" :: "r"(addr) : "memory")
#define MBAR_EXPECT_TX(addr, bytes) \
    asm volatile("mbarrier.arrive.expect_tx.shared.b64 _, [%0], %1;" \
                 :: "r"(addr), "r"(bytes) : "memory")

__device__ __forceinline__ void mbar_wait(uint32_t addr, uint32_t parity) {
    asm volatile(
        "{\n\t.reg .pred p;\n\t"
        "WAIT_%=:\n\t"
        "mbarrier.try_wait.parity.shared.b64 p, [%0], %1;\n\t"
        "@!p bra WAIT_%=;\n\t}"
        :: "r"(addr), "r"(parity) : "memory");
}

#define TMA2D(smem, map, x, y, mbar) \
    asm volatile("cp.async.bulk.tensor.2d.shared::cta.global.tile.mbarrier::complete_tx::bytes " \
                 "[%0], [%1, {%2, %3}], [%4];" \
                 :: "r"(smem), "l"(map), "r"(x), "r"(y), "r"(mbar) : "memory")

#define FENCE_ASYNC() asm volatile("fence.proxy.async.shared::cta;" ::: "memory")

// Swizzle matching CU_TENSOR_MAP_SWIZZLE_128B with 128B rows
// (r = row, ch = 16B chunk 0..7): byte_off ^ ((byte_off>>3)&0x70)
#define SWZ(r, ch) (((r) << 7) + ((((ch) ^ ((r) & 7))) << 4))

// ---------------------------------------------------------------------------
// Reductions
// ---------------------------------------------------------------------------
template <int BS>
__device__ __forceinline__ float blockReduce(float v, float* red) {
    int tid = threadIdx.x;
    red[tid] = v;
    __syncthreads();
#pragma unroll
    for (int s = BS / 2; s > 0; s >>= 1) {
        if (tid < s) red[tid] += red[tid + s];
        __syncthreads();
    }
    float out = red[0];
    __syncthreads();
    return out;
}

// 384-thread reduce: shfl within warp, 12-wide second stage.
__device__ __forceinline__ float fastReduce384(float v, volatile float* red,
                                               volatile float* bc) {
    int lane = threadIdx.x & 31, wid = threadIdx.x >> 5;
#pragma unroll
    for (int o = 16; o > 0; o >>= 1) v += __shfl_xor_sync(0xFFFFFFFFu, v, o);
    if (lane == 0) red[wid] = v;
    __syncthreads();
    if (wid == 0) {
        float x = (lane < 12) ? red[lane] : 0.0f;
#pragma unroll
        for (int o = 8; o > 0; o >>= 1) x += __shfl_xor_sync(0xFFFFFFFFu, x, o);
        if (lane == 0) *bc = x;
    }
    __syncthreads();
    return *bc;
}

// ---------------------------------------------------------------------------
// Grid barrier: sense-reversing, self-resetting counter + monotonic gen flag.
// ---------------------------------------------------------------------------
__device__ __forceinline__ void gridSync(unsigned& gen) {
    __syncthreads();
    if (threadIdx.x == 0) {
        __threadfence();
        unsigned target = gen + 1;
        unsigned old = atomicAdd(&g_cnt, 1);
        if (old == NCTA - 1) {
            g_cnt = 0;
            __threadfence();
            g_gen = target;
        } else {
            while (g_gen != target) { __nanosleep(32); }
        }
        __threadfence();
        gen = target;
    }
    __syncthreads();
}

// ---------------------------------------------------------------------------
// Round K to fp16 (once per launch)
// ---------------------------------------------------------------------------
__global__ void k_split(const float* __restrict__ K) {
    size_t i0 = (size_t)blockIdx.x * blockDim.x + threadIdx.x;
    size_t stride = (size_t)gridDim.x * blockDim.x;
    size_t n8 = (size_t)NN * NN / 8;
    for (size_t i = i0; i < n8; i += stride) {
        float4 a = ((const float4*)K)[2 * i];
        float4 b = ((const float4*)K)[2 * i + 1];
        union { __half h[8]; uint4 u; } H;
        H.h[0] = __float2half_rn(a.x); H.h[1] = __float2half_rn(a.y);
        H.h[2] = __float2half_rn(a.z); H.h[3] = __float2half_rn(a.w);
        H.h[4] = __float2half_rn(b.x); H.h[5] = __float2half_rn(b.y);
        H.h[6] = __float2half_rn(b.z); H.h[7] = __float2half_rn(b.w);
        ((uint4*)g_Khi16)[i] = H.u;
    }
}

// ---------------------------------------------------------------------------
// Init: B = [y | Z | 0-pad]; P = fp16(B) (scale 1), R = B, X = 0
// ---------------------------------------------------------------------------
__global__ void k_init(const float* __restrict__ y, const float* __restrict__ Z) {
    int stride = gridDim.x * blockDim.x;
    for (int idx = blockIdx.x * blockDim.x + threadIdx.x; idx < MP * NN; idx += stride) {
        int col = idx >> 13;
        int row = idx & (NN - 1);
        float v = 0.0f;
        if (col == 0)        v = y[row];
        else if (col <= 100) v = Z[row * 100 + (col - 1)];
        g_Ph16[idx] = __float2half_rn(v);
        g_R[idx] = v;
        if (col == 0) g_X[row] = 0.0f;
    }
}

// ---------------------------------------------------------------------------
// Split TMA producers (single thread). F = global monotonic fill index.
// full barrier gets TWO expect_tx arrivals per phase (K part + B part).
// ---------------------------------------------------------------------------
__device__ __forceinline__ void produceK(uint32_t sb, int F, int t_in_it,
                                         int kbase, int rb,
                                         const CUtensorMap* mK, bool waitEmpty) {
    uint32_t s = (uint32_t)(F % NSTG);
    if (waitEmpty && F >= NSTG)
        mbar_wait(sb + 64 + s * 8, (uint32_t)((F / NSTG - 1) & 1));
    FENCE_ASYNC();
    uint32_t full = sb + s * 8;
    MBAR_EXPECT_TX(full, (uint32_t)A_B);
    uint32_t st = sb + 1024 + s * STAGE_SP;
    TMA2D(st, mK, kbase + t_in_it * KT, rb, full);
}

__device__ __forceinline__ void produceB(uint32_t sb, int F, int t_in_it,
                                         int kbase, const CUtensorMap* mB) {
    uint32_t s = (uint32_t)(F % NSTG);
    uint32_t full = sb + s * 8;
    MBAR_EXPECT_TX(full, (uint32_t)B_TX);
    uint32_t st = sb + 1024 + s * STAGE_SP;
    TMA2D(st + A_B, mB, kbase + t_in_it * KT, 0, full);
}

// ---------------------------------------------------------------------------
// Persistent kernel: 30 x (GEMM phase -> gridSync -> update phase -> gridSync)
// 128 CTAs x 384 threads (1/SM). 12 warps = 4m x 3n, warp tile 64x40.
// ---------------------------------------------------------------------------
__global__ void __launch_bounds__(NTHR) k_persist(
        const __grid_constant__ CUtensorMap tmK,
        const __grid_constant__ CUtensorMap tmB) {
    extern __shared__ __align__(1024) char smem[];
    uint32_t sb = smem_u32(smem);
    volatile float* red = (volatile float*)(smem + 128);   // 12 floats
    volatile float* bcp = (volatile float*)(smem + 256);

    int tid = threadIdx.x, lane = tid & 31, w = tid >> 5;
    int wm = w & 3, wn = w >> 2;          // 4 m-bands x 3 n-bands
    int bid = blockIdx.x;
    int rb = (bid & 31) * ROWB;
    int ksp = bid >> 5;
    int kbase = ksp * KCHUNK;

    // init mbarriers: full[s] count 2 (K + B expect_tx), empty[s] count NTHR
    if (tid == 0) {
#pragma unroll
        for (int s = 0; s < NSTG; s++) {
            MBAR_INIT(sb + s * 8, 2u);
            MBAR_INIT(sb + 64 + s * 8, (uint32_t)NTHR);
        }
    }
    __syncthreads();

    unsigned gen = g_gen;   // safe: read before any barrier can complete

    int rA = wm * 64 + (lane & 15);
    int rB = wn * 40 + (lane & 15);
    int chHalf = lane >> 4;

    // per-column CG state in registers (uniform across the CTA)
    float rs = 0.0f, csc = 1.0f;
    if (bid < MREAL) {
        const float4* R4 = (const float4*)(g_R + (size_t)bid * NN);
        float s = 0.0f;
#pragma unroll
        for (int t = 0; t < 6; t++) {
            int i4 = t * NTHR + tid;
            if (i4 < NN / 4) {
                float4 rv = R4[i4];
                s += rv.x * rv.x + rv.y * rv.y + rv.z * rv.z + rv.w * rv.w;
            }
        }
        rs = fastReduce384(s, red, bcp);
    }
    __syncthreads();

    // prologue K fill for iteration 0 (buffers fresh -> no empty wait)
    if (tid == 0) {
#pragma unroll
        for (int s = 0; s < NSTG - 1; s++)
            produceK(sb, s, s, kbase, rb, &tmK, false);
    }

    for (int it = 0; it < PITER; it++) {
        int Fbase = it * KITERS;

        // B prologue: P is valid (post gridSync#2 of prev iter / k_init)
        if (tid == 0) {
#pragma unroll
            for (int s = 0; s < NSTG - 1; s++)
                produceB(sb, Fbase + s, s, kbase, &tmB);
        }

        // ------------------------------ GEMM phase ------------------------
        float acc[4][5][4];
#pragma unroll
        for (int mi = 0; mi < 4; mi++)
#pragma unroll
            for (int nj = 0; nj < 5; nj++)
#pragma unroll
                for (int q = 0; q < 4; q++) acc[mi][nj][q] = 0.0f;

        for (int t = 0; t < KITERS; t++) {
            int F = Fbase + t;
            if (tid == 0 && t + NSTG - 1 < KITERS) {
                produceK(sb, F + NSTG - 1, t + NSTG - 1, kbase, rb, &tmK, true);
                produceB(sb, F + NSTG - 1, t + NSTG - 1, kbase, &tmB);
            }

            uint32_t s = (uint32_t)(F % NSTG);
            mbar_wait(sb + s * 8, (uint32_t)((F / NSTG) & 1));
            uint32_t st = sb + 1024 + s * STAGE_SP;

#pragma unroll
            for (int kk = 0; kk < 4; kk++) {
                int ch = kk * 2 + chHalf;
                uint32_t ah[4][4], bh[3][4];
#pragma unroll
                for (int i = 0; i < 4; i++)
                    ldsm_x4(ah[i], st + SWZ(rA + i * 16, ch));
#pragma unroll
                for (int nb = 0; nb < 3; nb++)
                    ldsm_x4(bh[nb], st + A_B + SWZ(rB + nb * 16, ch));
#pragma unroll
                for (int mi = 0; mi < 4; mi++)
#pragma unroll
                    for (int nj = 0; nj < 5; nj++) {
                        int g = nj >> 1, sel = nj & 1;
                        mma16816(acc[mi][nj], ah[mi],
                                 bh[g][sel], bh[g][sel + 2]);
                    }
            }
            MBAR_ARRIVE(sb + 64 + s * 8);
        }

        // cross-iteration K prefetch: next iter's first stages (K only)
        if (tid == 0 && it + 1 < PITER) {
            int Fn = (it + 1) * KITERS;
#pragma unroll
            for (int s = 0; s < NSTG - 1; s++)
                produceK(sb, Fn + s, s, kbase, rb, &tmK, true);
        }

        {   // epilogue: scatter fp32 accumulators to Vpart (col-major)
            float* vp = g_Vpart + (size_t)ksp * MP * NN;
            int row0 = rb + wm * 64 + (lane >> 2);
            int col0 = wn * 40 + (lane & 3) * 2;
#pragma unroll
            for (int mi = 0; mi < 4; mi++)
#pragma unroll
                for (int nj = 0; nj < 5; nj++) {
                    int r_ = row0 + mi * 16;
                    int c_ = col0 + nj * 8;
                    vp[(size_t)c_ * NN + r_]           = acc[mi][nj][0];
                    vp[(size_t)(c_ + 1) * NN + r_]     = acc[mi][nj][1];
                    vp[(size_t)c_ * NN + r_ + 8]       = acc[mi][nj][2];
                    vp[(size_t)(c_ + 1) * NN + r_ + 8] = acc[mi][nj][3];
                }
        }

        gridSync(gen);   // Vpart complete before update reads it

        // ------------------------------ update phase ----------------------
        if (bid < MREAL) {
            int j = bid;
            const float4* V0 = (const float4*)g_Vpart + (size_t)j * NN / 4;
            const size_t PL = (size_t)MP * NN / 4;
            const float4* R4 = (const float4*)(g_R + (size_t)j * NN);
            const uint2* Ph2 = (const uint2*)(g_Ph16 + (size_t)j * NN);

            float4 p[6], v[6], r[6];
            float pv = 0.0f;
#pragma unroll
            for (int t = 0; t < 6; t++) {
                int i4 = t * NTHR + tid;
                if (i4 < NN / 4) {
                    float4 a = __ldcg(V0 + i4);
                    float4 b = __ldcg(V0 + PL + i4);
                    float4 d2 = __ldcg(V0 + 2 * PL + i4);
                    float4 e2 = __ldcg(V0 + 3 * PL + i4);
                    float4 s = make_float4(a.x + b.x + d2.x + e2.x,
                                           a.y + b.y + d2.y + e2.y,
                                           a.z + b.z + d2.z + e2.z,
                                           a.w + b.w + d2.w + e2.w);
                    v[t] = s;
                    uint2 hu = Ph2[i4];
                    __half2 h0 = *(__half2*)&hu.x, h1 = *(__half2*)&hu.y;
                    float2 f0 = __half22float2(h0), f1 = __half22float2(h1);
                    float4 pp = make_float4(f0.x, f0.y, f1.x, f1.y);
                    p[t] = pp;
                    pv += pp.x * s.x + pp.y * s.y + pp.z * s.z + pp.w * s.w;
                }
            }
            pv = fastReduce384(pv, red, bcp);      // = c^2 * (P.V)
            float alpha = rs * csc * csc / pv;
            float aoc = alpha / csc;

            float rr = 0.0f;
#pragma unroll
            for (int t = 0; t < 6; t++) {
                int i4 = t * NTHR + tid;
                if (i4 < NN / 4) {
                    float4 rv = R4[i4];
                    rv.x -= aoc * v[t].x; rv.y -= aoc * v[t].y;
                    rv.z -= aoc * v[t].z; rv.w -= aoc * v[t].w;
                    r[t] = rv;
                    rr += rv.x * rv.x + rv.y * rv.y + rv.z * rv.z + rv.w * rv.w;
                }
            }
            if (j == 0) {
                float4* X4 = (float4*)g_X;
#pragma unroll
                for (int t = 0; t < 6; t++) {
                    int i4 = t * NTHR + tid;
                    if (i4 < NN / 4) {
                        float4 x = X4[i4];
                        x.x += aoc * p[t].x; x.y += aoc * p[t].y;
                        x.z += aoc * p[t].z; x.w += aoc * p[t].w;
                        X4[i4] = x;
                    }
                }
            }
            rr = fastReduce384(rr, red, bcp);
            float beta = rr / rs;
            float c2 = exp2f(-rintf(0.5f * log2f(rr * (1.0f / (float)NN))));
            if (tid == 0) {
                g_alpha[it * MP + j] = alpha;
                g_beta[it * MP + j]  = beta;
            }
            float boc = beta / csc;

            uint2* Phw = (uint2*)(g_Ph16 + (size_t)j * NN);
            float4* Rw = (float4*)(g_R + (size_t)j * NN);
#pragma unroll
            for (int t = 0; t < 6; t++) {
                int i4 = t * NTHR + tid;
                if (i4 < NN / 4) {
                    float pn[4] = {
                        r[t].x + boc * p[t].x, r[t].y + boc * p[t].y,
                        r[t].z + boc * p[t].z, r[t].w + boc * p[t].w };
                    __half2 t0 = __floats2half2_rn(c2 * pn[0], c2 * pn[1]);
                    __half2 t1 = __floats2half2_rn(c2 * pn[2], c2 * pn[3]);
                    uint2 hu;
                    hu.x = *(uint32_t*)&t0; hu.y = *(uint32_t*)&t1;
                    Phw[i4] = hu;
                    Rw[i4] = r[t];
                }
            }
            rs = rr;
            csc = c2;
        }

        gridSync(gen);   // P complete before next GEMM's B loads / Vpart reuse
    }
}

// ---------------------------------------------------------------------------
// SLQ logdet (TQLI on 30x30 tridiagonal, first-row eigenvector weights)
// ---------------------------------------------------------------------------
__device__ void tqli30(double* d, double* e, double* z) {
    const int n = PITER;
    for (int l = 0; l < n; l++) {
        int iter = 0;
        int m;
        do {
            for (m = l; m < n - 1; m++) {
                double dd = fabs(d[m]) + fabs(d[m + 1]);
                if (fabs(e[m]) <= 2.3e-16 * dd) break;
            }
            if (m != l) {
                if (iter++ == 64) break;
                double g = (d[l + 1] - d[l]) / (2.0 * e[l]);
                double rr = sqrt(g * g + 1.0);
                double sg = (g >= 0.0) ? rr : -rr;
                g = d[m] - d[l] + e[l] / (g + sg);
                double s = 1.0, cc = 1.0, p = 0.0;
                bool under = false;
                for (int i = m - 1; i >= l; i--) {
                    double f = s * e[i];
                    double b = cc * e[i];
                    double rq = sqrt(f * f + g * g);
                    e[i + 1] = rq;
                    if (rq == 0.0) {
                        d[i + 1] -= p;
                        e[m] = 0.0;
                        under = true;
                        break;
                    }
                    s = f / rq; cc = g / rq;
                    g = d[i + 1] - p;
                    rq = (d[i] - g) * s + 2.0 * cc * b;
                    p = s * rq;
                    d[i + 1] = g + p;
                    g = cc * rq - b;
                    double zi = z[i], zi1 = z[i + 1];
                    z[i + 1] = s * zi + cc * zi1;
                    z[i]     = cc * zi - s * zi1;
                }
                if (under) continue;
                d[l] -= p;
                e[l] = g;
                e[m] = 0.0;
            }
        } while (m != l);
    }
}

__global__ void k_logdet() {
    __shared__ double qsum[128];
    int tid = threadIdx.x;
    double quad = 0.0;
    if (tid < 100) {
        int j = tid + 1;
        double d[PITER], e[PITER], z[PITER];
        double pa = 1.0, pb = 0.0;
        for (int k = 0; k < PITER; k++) {
            double a = (double)g_alpha[k * MP + j];
            double b = (double)g_beta[k * MP + j];
            d[k] = 1.0 / a + ((k > 0) ? pb / pa : 0.0);
            e[k] = (k < PITER - 1) ? sqrt(b) / a : 0.0;
            z[k] = (k == 0) ? 1.0 : 0.0;
            pa = a; pb = b;
        }
        tqli30(d, e, z);
        for (int k = 0; k < PITER; k++) {
            double lam = d[k] < 1e-12 ? 1e-12 : d[k];
            quad += z[k] * z[k] * log(lam);
        }
    }
    qsum[tid] = quad;
    __syncthreads();
    if (tid == 0) {
        double s = 0.0;
        for (int i = 0; i < 100; i++) s += qsum[i];
        g_logdet = (float)((double)NN * s / 100.0);
    }
}

__global__ void k_final(const float* __restrict__ y, float* __restrict__ out) {
    __shared__ float red[256];
    float s = 0.0f;
    for (int i = threadIdx.x; i < NN; i += 256) s += y[i] * g_X[i];
    s = blockReduce<256>(s, red);
    if (threadIdx.x == 0) {
        const double LOG2PI = 1.8378770664093454836;
        double r = -0.5 * (double)s - 0.5 * (double)g_logdet - 0.5 * (double)NN * LOG2PI;
        out[0] = (float)r;
    }
}

// ---------------------------------------------------------------------------
// Launch: build TensorMaps via driver entry point (cudart-only), then chain.
// ---------------------------------------------------------------------------
typedef CUresult (*PFN_encodeTiled)(
    CUtensorMap*, CUtensorMapDataType, cuuint32_t, void*,
    const cuuint64_t*, const cuuint64_t*, const cuuint32_t*, const cuuint32_t*,
    CUtensorMapInterleave, CUtensorMapSwizzle, CUtensorMapL2promotion,
    CUtensorMapFloatOOBfill);

extern "C" void kernel_launch(void* const* d_in, const int* in_sizes, int n_in,
                              void* d_out, int out_size) {
    const float* K = (const float*)d_in[0];
    const float* y = (const float*)d_in[1];
    const float* Z = (const float*)d_in[2];
    float* out = (float*)d_out;

    // resolve cuTensorMapEncodeTiled through cudart (no -lcuda needed)
    void* fn = nullptr;
    cudaDriverEntryPointQueryResult qres;
    cudaGetDriverEntryPointByVersion("cuTensorMapEncodeTiled", &fn, 12000,
                                     cudaEnableDefault, &qres);
    PFN_encodeTiled enc = (PFN_encodeTiled)fn;

    void *pK = nullptr, *pPh = nullptr;
    cudaGetSymbolAddress(&pK, g_Khi16);
    cudaGetSymbolAddress(&pPh, g_Ph16);

    CUtensorMap tmK, tmB;
    {
        cuuint64_t dims[2] = {NN, NN};
        cuuint64_t strides[1] = {NN * 2};
        cuuint32_t box[2] = {64, 256};
        cuuint32_t es[2] = {1, 1};
        enc(&tmK, CU_TENSOR_MAP_DATA_TYPE_FLOAT16, 2, pK, dims, strides, box, es,
            CU_TENSOR_MAP_INTERLEAVE_NONE, CU_TENSOR_MAP_SWIZZLE_128B,
            CU_TENSOR_MAP_L2_PROMOTION_L2_128B, CU_TENSOR_MAP_FLOAT_OOB_FILL_NONE);
    }
    {
        cuuint64_t dims[2] = {NN, MP};
        cuuint64_t strides[1] = {NN * 2};
        cuuint32_t box[2] = {64, NCOLS};
        cuuint32_t es[2] = {1, 1};
        enc(&tmB, CU_TENSOR_MAP_DATA_TYPE_FLOAT16, 2, pPh, dims, strides, box, es,
            CU_TENSOR_MAP_INTERLEAVE_NONE, CU_TENSOR_MAP_SWIZZLE_128B,
            CU_TENSOR_MAP_L2_PROMOTION_L2_128B, CU_TENSOR_MAP_FLOAT_OOB_FILL_NONE);
    }

    cudaFuncSetAttribute(k_persist, cudaFuncAttributeMaxDynamicSharedMemorySize,
                         SMEM_DYN);

    k_split<<<4096, 256>>>(K);
    k_init<<<512, 256>>>(y, Z);
    k_persist<<<NCTA, NTHR, SMEM_DYN>>>(tmK, tmB);
    k_logdet<<<1, 128>>>();
    k_final<<<1, 256>>>(y, out);
}

// round 16
// speedup vs baseline: 1.0402x; 1.0402x over previous
#include <cuda.h>
#include <cuda_runtime.h>
#include <cuda_fp16.h>
#include <math.h>
#include <stdint.h>

// ---------------------------------------------------------------------------
// Problem constants
// ---------------------------------------------------------------------------
#define NN      8192
#define MREAL   101
#define MP      128
#define NCOLS   112                  // computed columns (14 x 8), >= MREAL
#define PITER   30
#define KSPLIT  4
#define KCHUNK  (NN / KSPLIT)        // 2048
#define KT      64                   // k per pipeline stage
#define KITERS  (KCHUNK / KT)        // 32
#define NSTG    4
#define ROWB    256
#define NTHR    256
#define NCTA    128                  // 32 rowblocks x KSPLIT, 1 CTA/SM
#define A_B     (ROWB * KT * 2)      // 32768 B: A tile (256 rows x 64 k fp16)
#define B_TX    (NCOLS * KT * 2)     // 14336 B actually transferred
#define B_SP    (128 * KT * 2)       // 16384 B reserved (ldsm overread pad)
#define STAGE_SP (A_B + B_SP)        // 49152 B
#define SMEM_DYN (1024 + NSTG * STAGE_SP)   // 197632 B

// ---------------------------------------------------------------------------
// Scratch (static device globals; no allocation allowed)
// ---------------------------------------------------------------------------
__device__ __half g_Khi16[(size_t)NN * NN];     // 128 MB: fp16-rounded K
__device__ __half g_Ph16[(size_t)MP * NN];      // scaled fp16 P, col-major
__device__ float  g_R[(size_t)MP * NN];         // initial residual (k_init only)
__device__ float  g_X[NN];
__device__ float  g_Vpart[(size_t)KSPLIT * MP * NN];  // 16 MB
__device__ float  g_alpha[PITER * MP];
__device__ float  g_beta[PITER * MP];
__device__ float  g_logdet;

// grid barrier state (self-resetting; g_gen monotonic across graph replays)
__device__ unsigned g_cnt = 0;
__device__ volatile unsigned g_gen = 0;

// ---------------------------------------------------------------------------
// PTX helpers (family-portable: ldmatrix / mma.sync / TMA / mbarrier)
// ---------------------------------------------------------------------------
__device__ __forceinline__ uint32_t smem_u32(const void* p) {
    uint32_t a;
    asm("{ .reg .u64 t; cvta.to.shared.u64 t, %1; cvt.u32.u64 %0, t; }"
        : "=r"(a) : "l"(p));
    return a;
}

__device__ __forceinline__ void ldsm_x4(uint32_t (&r)[4], uint32_t addr) {
    asm volatile("ldmatrix.sync.aligned.m8n8.x4.shared.b16 {%0,%1,%2,%3}, [%4];"
        : "=r"(r[0]), "=r"(r[1]), "=r"(r[2]), "=r"(r[3]) : "r"(addr));
}

__device__ __forceinline__ void mma16816(float (&d)[4], const uint32_t (&a)[4],
                                         uint32_t b0, uint32_t b1) {
    asm volatile("mma.sync.aligned.m16n8k16.row.col.f32.f16.f16.f32 "
        "{%0,%1,%2,%3}, {%4,%5,%6,%7}, {%8,%9}, {%0,%1,%2,%3};"
        : "+f"(d[0]), "+f"(d[1]), "+f"(d[2]), "+f"(d[3])
        : "r"(a[0]), "r"(a[1]), "r"(a[2]), "r"(a[3]), "r"(b0), "r"(b1));
}

#define MBAR_INIT(addr, cnt) \
    asm volatile("mbarrier.init.shared.b64 [%0], %1;" :: "r"(addr), "r"(cnt) : "memory")
#define MBAR_ARRIVE(addr) \
    asm volatile("mbarrier.arrive.shared.b64 _, [%0];" :: "r"(addr) : "memory")
#define MBAR_EXPECT_TX(addr, bytes) \
    asm volatile("mbarrier.arrive.expect_tx.shared.b64 _, [%0], %1;" \
                 :: "r"(addr), "r"(bytes) : "memory")

__device__ __forceinline__ void mbar_wait(uint32_t addr, uint32_t parity) {
    asm volatile(
        "{\n\t.reg .pred p;\n\t"
        "WAIT_%=:\n\t"
        "mbarrier.try_wait.parity.shared.b64 p, [%0], %1;\n\t"
        "@!p bra WAIT_%=;\n\t}"
        :: "r"(addr), "r"(parity) : "memory");
}

#define TMA2D(smem, map, x, y, mbar) \
    asm volatile("cp.async.bulk.tensor.2d.shared::cta.global.tile.mbarrier::complete_tx::bytes " \
                 "[%0], [%1, {%2, %3}], [%4];" \
                 :: "r"(smem), "l"(map), "r"(x), "r"(y), "r"(mbar) : "memory")

#define FENCE_ASYNC() asm volatile("fence.proxy.async.shared::cta;" ::: "memory")

// Swizzle matching CU_TENSOR_MAP_SWIZZLE_128B with 128B rows
// (r = row, ch = 16B chunk 0..7): byte_off ^ ((byte_off>>3)&0x70)
#define SWZ(r, ch) (((r) << 7) + ((((ch) ^ ((r) & 7))) << 4))

// ---------------------------------------------------------------------------
// Reductions
// ---------------------------------------------------------------------------
template <int BS>
__device__ __forceinline__ float blockReduce(float v, float* red) {
    int tid = threadIdx.x;
    red[tid] = v;
    __syncthreads();
#pragma unroll
    for (int s = BS / 2; s > 0; s >>= 1) {
        if (tid < s) red[tid] += red[tid + s];
        __syncthreads();
    }
    float out = red[0];
    __syncthreads();
    return out;
}

__device__ __forceinline__ float fastReduce256(float v, volatile float* red,
                                               volatile float* bc) {
    int lane = threadIdx.x & 31, wid = threadIdx.x >> 5;
#pragma unroll
    for (int o = 16; o > 0; o >>= 1) v += __shfl_xor_sync(0xFFFFFFFFu, v, o);
    if (lane == 0) red[wid] = v;
    __syncthreads();
    if (wid == 0) {
        float x = (lane < 8) ? red[lane] : 0.0f;
#pragma unroll
        for (int o = 4; o > 0; o >>= 1) x += __shfl_xor_sync(0xFFFFFFFFu, x, o);
        if (lane == 0) *bc = x;
    }
    __syncthreads();
    return *bc;
}

// ---------------------------------------------------------------------------
// Grid barrier: sense-reversing, self-resetting counter + monotonic gen flag.
// ---------------------------------------------------------------------------
__device__ __forceinline__ void gridSync(unsigned& gen) {
    __syncthreads();
    if (threadIdx.x == 0) {
        __threadfence();
        unsigned target = gen + 1;
        unsigned old = atomicAdd(&g_cnt, 1);
        if (old == NCTA - 1) {
            g_cnt = 0;
            __threadfence();
            g_gen = target;
        } else {
            while (g_gen != target) { __nanosleep(32); }
        }
        __threadfence();
        gen = target;
    }
    __syncthreads();
}

// ---------------------------------------------------------------------------
// Round K to fp16 (once per launch)
// ---------------------------------------------------------------------------
__global__ void k_split(const float* __restrict__ K) {
    size_t i0 = (size_t)blockIdx.x * blockDim.x + threadIdx.x;
    size_t stride = (size_t)gridDim.x * blockDim.x;
    size_t n8 = (size_t)NN * NN / 8;
    for (size_t i = i0; i < n8; i += stride) {
        float4 a = ((const float4*)K)[2 * i];
        float4 b = ((const float4*)K)[2 * i + 1];
        union { __half h[8]; uint4 u; } H;
        H.h[0] = __float2half_rn(a.x); H.h[1] = __float2half_rn(a.y);
        H.h[2] = __float2half_rn(a.z); H.h[3] = __float2half_rn(a.w);
        H.h[4] = __float2half_rn(b.x); H.h[5] = __float2half_rn(b.y);
        H.h[6] = __float2half_rn(b.z); H.h[7] = __float2half_rn(b.w);
        ((uint4*)g_Khi16)[i] = H.u;
    }
}

// ---------------------------------------------------------------------------
// Init: B = [y | Z | 0-pad]; P = fp16(B) (scale 1), R = B, X = 0
// ---------------------------------------------------------------------------
__global__ void k_init(const float* __restrict__ y, const float* __restrict__ Z) {
    int stride = gridDim.x * blockDim.x;
    for (int idx = blockIdx.x * blockDim.x + threadIdx.x; idx < MP * NN; idx += stride) {
        int col = idx >> 13;
        int row = idx & (NN - 1);
        float v = 0.0f;
        if (col == 0)        v = y[row];
        else if (col <= 100) v = Z[row * 100 + (col - 1)];
        g_Ph16[idx] = __float2half_rn(v);
        g_R[idx] = v;
        if (col == 0) g_X[row] = 0.0f;
    }
}

// ---------------------------------------------------------------------------
// Split TMA producers (single thread). F = global monotonic fill index.
// full barrier gets TWO expect_tx arrivals per phase (K part + B part).
// ---------------------------------------------------------------------------
__device__ __forceinline__ void produceK(uint32_t sb, int F, int t_in_it,
                                         int kbase, int rb,
                                         const CUtensorMap* mK, bool waitEmpty) {
    uint32_t s = (uint32_t)(F % NSTG);
    if (waitEmpty && F >= NSTG)
        mbar_wait(sb + 64 + s * 8, (uint32_t)((F / NSTG - 1) & 1));
    FENCE_ASYNC();
    uint32_t full = sb + s * 8;
    MBAR_EXPECT_TX(full, (uint32_t)A_B);
    uint32_t st = sb + 1024 + s * STAGE_SP;
    TMA2D(st, mK, kbase + t_in_it * KT, rb, full);
}

__device__ __forceinline__ void produceB(uint32_t sb, int F, int t_in_it,
                                         int kbase, const CUtensorMap* mB) {
    uint32_t s = (uint32_t)(F % NSTG);
    uint32_t full = sb + s * 8;
    MBAR_EXPECT_TX(full, (uint32_t)B_TX);
    uint32_t st = sb + 1024 + s * STAGE_SP;
    TMA2D(st + A_B, mB, kbase + t_in_it * KT, 0, full);
}

// ---------------------------------------------------------------------------
// Persistent kernel: 30 x (GEMM phase -> gridSync -> update phase -> gridSync)
// 128 CTAs x 256 threads (1/SM). Warp tile 64x56, double-buffered operands.
// Residual R lives in registers for the whole loop (no global R traffic).
// ---------------------------------------------------------------------------
__global__ void __launch_bounds__(NTHR) k_persist(
        const __grid_constant__ CUtensorMap tmK,
        const __grid_constant__ CUtensorMap tmB) {
    extern __shared__ __align__(1024) char smem[];
    uint32_t sb = smem_u32(smem);
    volatile float* red = (volatile float*)(smem + 128);   // 8 floats
    volatile float* bcp = (volatile float*)(smem + 256);

    int tid = threadIdx.x, lane = tid & 31, w = tid >> 5;
    int wm = w & 3, wn = w >> 2;          // 4 m-bands x 2 n-bands
    int bid = blockIdx.x;
    int rb = (bid & 31) * ROWB;
    int ksp = bid >> 5;
    int kbase = ksp * KCHUNK;

    // init mbarriers: full[s] count 2 (K + B expect_tx), empty[s] count NTHR
    if (tid == 0) {
#pragma unroll
        for (int s = 0; s < NSTG; s++) {
            MBAR_INIT(sb + s * 8, 2u);
            MBAR_INIT(sb + 64 + s * 8, (uint32_t)NTHR);
        }
    }
    __syncthreads();

    unsigned gen = g_gen;   // safe: read before any barrier can complete

    int rA = wm * 64 + (lane & 15);
    int rB = wn * 56 + (lane & 15);
    int chHalf = lane >> 4;

    // per-column CG state: residual R in registers (8 float4 = 32 regs),
    // scalars rs / scale uniform across the CTA
    float4 Rreg[8];
    float rs = 0.0f, csc = 1.0f;
    if (bid < MREAL) {
        const float4* R4 = (const float4*)(g_R + (size_t)bid * NN);
        float s = 0.0f;
#pragma unroll
        for (int t = 0; t < 8; t++) {
            float4 rv = R4[t * NTHR + tid];
            Rreg[t] = rv;
            s += rv.x * rv.x + rv.y * rv.y + rv.z * rv.z + rv.w * rv.w;
        }
        rs = fastReduce256(s, red, bcp);
    }
    __syncthreads();

    // prologue K fill for iteration 0 (buffers fresh -> no empty wait)
    if (tid == 0) {
#pragma unroll
        for (int s = 0; s < NSTG - 1; s++)
            produceK(sb, s, s, kbase, rb, &tmK, false);
    }

    for (int it = 0; it < PITER; it++) {
        int Fbase = it * KITERS;

        // B prologue: P is valid (post gridSync#2 of prev iter / k_init)
        if (tid == 0) {
#pragma unroll
            for (int s = 0; s < NSTG - 1; s++)
                produceB(sb, Fbase + s, s, kbase, &tmB);
        }

        // ------------------------------ GEMM phase ------------------------
        float acc[4][7][4];
#pragma unroll
        for (int mi = 0; mi < 4; mi++)
#pragma unroll
            for (int nj = 0; nj < 7; nj++)
#pragma unroll
                for (int q = 0; q < 4; q++) acc[mi][nj][q] = 0.0f;

        for (int t = 0; t < KITERS; t++) {
            int F = Fbase + t;
            if (tid == 0 && t + NSTG - 1 < KITERS) {
                produceK(sb, F + NSTG - 1, t + NSTG - 1, kbase, rb, &tmK, true);
                produceB(sb, F + NSTG - 1, t + NSTG - 1, kbase, &tmB);
            }

            uint32_t s = (uint32_t)(F % NSTG);
            mbar_wait(sb + s * 8, (uint32_t)((F / NSTG) & 1));
            uint32_t st = sb + 1024 + s * STAGE_SP;

            // software-pipelined operands: prefetch kk+1 before kk's MMAs
            uint32_t ah[2][4][4], bh[2][4][4];
            {
                int ch = chHalf;
#pragma unroll
                for (int i = 0; i < 4; i++)
                    ldsm_x4(ah[0][i], st + SWZ(rA + i * 16, ch));
#pragma unroll
                for (int nb = 0; nb < 4; nb++)
                    ldsm_x4(bh[0][nb], st + A_B + SWZ(rB + nb * 16, ch));
            }
#pragma unroll
            for (int kk = 0; kk < 4; kk++) {
                int cur = kk & 1, nxt = cur ^ 1;
                if (kk < 3) {
                    int ch = (kk + 1) * 2 + chHalf;
#pragma unroll
                    for (int i = 0; i < 4; i++)
                        ldsm_x4(ah[nxt][i], st + SWZ(rA + i * 16, ch));
#pragma unroll
                    for (int nb = 0; nb < 4; nb++)
                        ldsm_x4(bh[nxt][nb], st + A_B + SWZ(rB + nb * 16, ch));
                }
#pragma unroll
                for (int mi = 0; mi < 4; mi++)
#pragma unroll
                    for (int nj = 0; nj < 7; nj++) {
                        int g = nj >> 1, sel = nj & 1;
                        mma16816(acc[mi][nj], ah[cur][mi],
                                 bh[cur][g][sel], bh[cur][g][sel + 2]);
                    }
            }
            MBAR_ARRIVE(sb + 64 + s * 8);
        }

        // cross-iteration K prefetch: next iter's first stages (K only)
        if (tid == 0 && it + 1 < PITER) {
            int Fn = (it + 1) * KITERS;
#pragma unroll
            for (int s = 0; s < NSTG - 1; s++)
                produceK(sb, Fn + s, s, kbase, rb, &tmK, true);
        }

        {   // epilogue: scatter fp32 accumulators to Vpart (col-major)
            float* vp = g_Vpart + (size_t)ksp * MP * NN;
            int row0 = rb + wm * 64 + (lane >> 2);
            int col0 = wn * 56 + (lane & 3) * 2;
#pragma unroll
            for (int mi = 0; mi < 4; mi++)
#pragma unroll
                for (int nj = 0; nj < 7; nj++) {
                    int r_ = row0 + mi * 16;
                    int c_ = col0 + nj * 8;
                    vp[(size_t)c_ * NN + r_]           = acc[mi][nj][0];
                    vp[(size_t)(c_ + 1) * NN + r_]     = acc[mi][nj][1];
                    vp[(size_t)c_ * NN + r_ + 8]       = acc[mi][nj][2];
                    vp[(size_t)(c_ + 1) * NN + r_ + 8] = acc[mi][nj][3];
                }
        }

        gridSync(gen);   // Vpart complete before update reads it

        // ------------------------------ update phase ----------------------
        if (bid < MREAL) {
            int j = bid;
            const float4* V0 = (const float4*)g_Vpart + (size_t)j * NN / 4;
            const size_t PL = (size_t)MP * NN / 4;
            const uint2* Ph2 = (const uint2*)(g_Ph16 + (size_t)j * NN);

            float4 p[8], v[8];
            float pv = 0.0f;
#pragma unroll
            for (int t = 0; t < 8; t++) {
                int i4 = t * NTHR + tid;
                float4 a = __ldcg(V0 + i4);
                float4 b = __ldcg(V0 + PL + i4);
                float4 d2 = __ldcg(V0 + 2 * PL + i4);
                float4 e2 = __ldcg(V0 + 3 * PL + i4);
                float4 s = make_float4(a.x + b.x + d2.x + e2.x,
                                       a.y + b.y + d2.y + e2.y,
                                       a.z + b.z + d2.z + e2.z,
                                       a.w + b.w + d2.w + e2.w);
                v[t] = s;
                uint2 hu = Ph2[i4];
                __half2 h0 = *(__half2*)&hu.x, h1 = *(__half2*)&hu.y;
                float2 f0 = __half22float2(h0), f1 = __half22float2(h1);
                float4 pp = make_float4(f0.x, f0.y, f1.x, f1.y);
                p[t] = pp;
                pv += pp.x * s.x + pp.y * s.y + pp.z * s.z + pp.w * s.w;
            }
            pv = fastReduce256(pv, red, bcp);      // = c^2 * (P.V)
            float alpha = rs * csc * csc / pv;
            float aoc = alpha / csc;

            float rr = 0.0f;
#pragma unroll
            for (int t = 0; t < 8; t++) {
                float4 rv = Rreg[t];
                rv.x -= aoc * v[t].x; rv.y -= aoc * v[t].y;
                rv.z -= aoc * v[t].z; rv.w -= aoc * v[t].w;
                Rreg[t] = rv;
                rr += rv.x * rv.x + rv.y * rv.y + rv.z * rv.z + rv.w * rv.w;
            }
            if (j == 0) {
                float4* X4 = (float4*)g_X;
#pragma unroll
                for (int t = 0; t < 8; t++) {
                    int i4 = t * NTHR + tid;
                    float4 x = X4[i4];
                    x.x += aoc * p[t].x; x.y += aoc * p[t].y;
                    x.z += aoc * p[t].z; x.w += aoc * p[t].w;
                    X4[i4] = x;
                }
            }
            rr = fastReduce256(rr, red, bcp);
            float beta = rr / rs;
            float c2 = exp2f(-rintf(0.5f * log2f(rr * (1.0f / (float)NN))));
            if (tid == 0) {
                g_alpha[it * MP + j] = alpha;
                g_beta[it * MP + j]  = beta;
            }
            float boc = beta / csc;

            uint2* Phw = (uint2*)(g_Ph16 + (size_t)j * NN);
#pragma unroll
            for (int t = 0; t < 8; t++) {
                int i4 = t * NTHR + tid;
                float pn[4] = {
                    Rreg[t].x + boc * p[t].x, Rreg[t].y + boc * p[t].y,
                    Rreg[t].z + boc * p[t].z, Rreg[t].w + boc * p[t].w };
                __half2 t0 = __floats2half2_rn(c2 * pn[0], c2 * pn[1]);
                __half2 t1 = __floats2half2_rn(c2 * pn[2], c2 * pn[3]);
                uint2 hu;
                hu.x = *(uint32_t*)&t0; hu.y = *(uint32_t*)&t1;
                Phw[i4] = hu;
            }
            rs = rr;
            csc = c2;
        }

        gridSync(gen);   // P complete before next GEMM's B loads / Vpart reuse
    }
}

// ---------------------------------------------------------------------------
// SLQ logdet (TQLI on 30x30 tridiagonal, first-row eigenvector weights)
// ---------------------------------------------------------------------------
__device__ void tqli30(double* d, double* e, double* z) {
    const int n = PITER;
    for (int l = 0; l < n; l++) {
        int iter = 0;
        int m;
        do {
            for (m = l; m < n - 1; m++) {
                double dd = fabs(d[m]) + fabs(d[m + 1]);
                if (fabs(e[m]) <= 2.3e-16 * dd) break;
            }
            if (m != l) {
                if (iter++ == 64) break;
                double g = (d[l + 1] - d[l]) / (2.0 * e[l]);
                double rr = sqrt(g * g + 1.0);
                double sg = (g >= 0.0) ? rr : -rr;
                g = d[m] - d[l] + e[l] / (g + sg);
                double s = 1.0, cc = 1.0, p = 0.0;
                bool under = false;
                for (int i = m - 1; i >= l; i--) {
                    double f = s * e[i];
                    double b = cc * e[i];
                    double rq = sqrt(f * f + g * g);
                    e[i + 1] = rq;
                    if (rq == 0.0) {
                        d[i + 1] -= p;
                        e[m] = 0.0;
                        under = true;
                        break;
                    }
                    s = f / rq; cc = g / rq;
                    g = d[i + 1] - p;
                    rq = (d[i] - g) * s + 2.0 * cc * b;
                    p = s * rq;
                    d[i + 1] = g + p;
                    g = cc * rq - b;
                    double zi = z[i], zi1 = z[i + 1];
                    z[i + 1] = s * zi + cc * zi1;
                    z[i]     = cc * zi - s * zi1;
                }
                if (under) continue;
                d[l] -= p;
                e[l] = g;
                e[m] = 0.0;
            }
        } while (m != l);
    }
}

__global__ void k_logdet() {
    __shared__ double qsum[128];
    int tid = threadIdx.x;
    double quad = 0.0;
    if (tid < 100) {
        int j = tid + 1;
        double d[PITER], e[PITER], z[PITER];
        double pa = 1.0, pb = 0.0;
        for (int k = 0; k < PITER; k++) {
            double a = (double)g_alpha[k * MP + j];
            double b = (double)g_beta[k * MP + j];
            d[k] = 1.0 / a + ((k > 0) ? pb / pa : 0.0);
            e[k] = (k < PITER - 1) ? sqrt(b) / a : 0.0;
            z[k] = (k == 0) ? 1.0 : 0.0;
            pa = a; pb = b;
        }
        tqli30(d, e, z);
        for (int k = 0; k < PITER; k++) {
            double lam = d[k] < 1e-12 ? 1e-12 : d[k];
            quad += z[k] * z[k] * log(lam);
        }
    }
    qsum[tid] = quad;
    __syncthreads();
    if (tid == 0) {
        double s = 0.0;
        for (int i = 0; i < 100; i++) s += qsum[i];
        g_logdet = (float)((double)NN * s / 100.0);
    }
}

__global__ void k_final(const float* __restrict__ y, float* __restrict__ out) {
    __shared__ float red[256];
    float s = 0.0f;
    for (int i = threadIdx.x; i < NN; i += 256) s += y[i] * g_X[i];
    s = blockReduce<256>(s, red);
    if (threadIdx.x == 0) {
        const double LOG2PI = 1.8378770664093454836;
        double r = -0.5 * (double)s - 0.5 * (double)g_logdet - 0.5 * (double)NN * LOG2PI;
        out[0] = (float)r;
    }
}

// ---------------------------------------------------------------------------
// Launch: build TensorMaps via driver entry point (cudart-only), then chain.
// ---------------------------------------------------------------------------
typedef CUresult (*PFN_encodeTiled)(
    CUtensorMap*, CUtensorMapDataType, cuuint32_t, void*,
    const cuuint64_t*, const cuuint64_t*, const cuuint32_t*, const cuuint32_t*,
    CUtensorMapInterleave, CUtensorMapSwizzle, CUtensorMapL2promotion,
    CUtensorMapFloatOOBfill);

extern "C" void kernel_launch(void* const* d_in, const int* in_sizes, int n_in,
                              void* d_out, int out_size) {
    const float* K = (const float*)d_in[0];
    const float* y = (const float*)d_in[1];
    const float* Z = (const float*)d_in[2];
    float* out = (float*)d_out;

    // resolve cuTensorMapEncodeTiled through cudart (no -lcuda needed)
    void* fn = nullptr;
    cudaDriverEntryPointQueryResult qres;
    cudaGetDriverEntryPointByVersion("cuTensorMapEncodeTiled", &fn, 12000,
                                     cudaEnableDefault, &qres);
    PFN_encodeTiled enc = (PFN_encodeTiled)fn;

    void *pK = nullptr, *pPh = nullptr;
    cudaGetSymbolAddress(&pK, g_Khi16);
    cudaGetSymbolAddress(&pPh, g_Ph16);

    CUtensorMap tmK, tmB;
    {
        cuuint64_t dims[2] = {NN, NN};
        cuuint64_t strides[1] = {NN * 2};
        cuuint32_t box[2] = {64, 256};
        cuuint32_t es[2] = {1, 1};
        enc(&tmK, CU_TENSOR_MAP_DATA_TYPE_FLOAT16, 2, pK, dims, strides, box, es,
            CU_TENSOR_MAP_INTERLEAVE_NONE, CU_TENSOR_MAP_SWIZZLE_128B,
            CU_TENSOR_MAP_L2_PROMOTION_L2_128B, CU_TENSOR_MAP_FLOAT_OOB_FILL_NONE);
    }
    {
        cuuint64_t dims[2] = {NN, MP};
        cuuint64_t strides[1] = {NN * 2};
        cuuint32_t box[2] = {64, NCOLS};
        cuuint32_t es[2] = {1, 1};
        enc(&tmB, CU_TENSOR_MAP_DATA_TYPE_FLOAT16, 2, pPh, dims, strides, box, es,
            CU_TENSOR_MAP_INTERLEAVE_NONE, CU_TENSOR_MAP_SWIZZLE_128B,
            CU_TENSOR_MAP_L2_PROMOTION_L2_128B, CU_TENSOR_MAP_FLOAT_OOB_FILL_NONE);
    }

    cudaFuncSetAttribute(k_persist, cudaFuncAttributeMaxDynamicSharedMemorySize,
                         SMEM_DYN);

    k_split<<<4096, 256>>>(K);
    k_init<<<512, 256>>>(y, Z);
    k_persist<<<NCTA, NTHR, SMEM_DYN>>>(tmK, tmB);
    k_logdet<<<1, 128>>>();
    k_final<<<1, 256>>>(y, out);
}

// round 17
// speedup vs baseline: 1.0470x; 1.0065x over previous
#include <cuda.h>
#include <cuda_runtime.h>
#include <cuda_fp16.h>
#include <math.h>
#include <stdint.h>

// ---------------------------------------------------------------------------
// Problem constants
// ---------------------------------------------------------------------------
#define NN      8192
#define MREAL   101
#define MP      128
#define NCOLS   112                  // computed columns (14 x 8), >= MREAL
#define PITER   30
#define KSPLIT  4
#define KCHUNK  (NN / KSPLIT)        // 2048
#define KT      64                   // k per pipeline stage
#define KITERS  (KCHUNK / KT)        // 32
#define NSTG    4
#define ROWB    256
#define NTHR    256
#define NCTA    128                  // 32 rowblocks x KSPLIT, 1 CTA/SM
#define A_B     (ROWB * KT * 2)      // 32768 B: A tile (256 rows x 64 k fp16)
#define B_TX    (NCOLS * KT * 2)     // 14336 B actually transferred
#define B_SP    (128 * KT * 2)       // 16384 B reserved (ldsm overread pad)
#define STAGE_SP (A_B + B_SP)        // 49152 B
#define SMEM_DYN (1024 + NSTG * STAGE_SP)   // 197632 B

// ---------------------------------------------------------------------------
// Scratch (static device globals; no allocation allowed)
// ---------------------------------------------------------------------------
__device__ __half g_Khi16[(size_t)NN * NN];     // 128 MB: fp16-rounded K
__device__ __half g_Ph16[(size_t)MP * NN];      // scaled fp16 P, col-major
__device__ float  g_R[(size_t)MP * NN];         // initial residual (k_init only)
__device__ float  g_X[NN];
__device__ float  g_Vpart[(size_t)KSPLIT * MP * NN];  // 16 MB
__device__ float  g_alpha[PITER * MP];
__device__ float  g_beta[PITER * MP];
__device__ float  g_logdet;

// grid barrier + update-completion counter (monotonic across graph replays)
__device__ unsigned g_cnt = 0;
__device__ volatile unsigned g_gen = 0;
__device__ volatile unsigned g_done = 0;

// ---------------------------------------------------------------------------
// PTX helpers (family-portable: ldmatrix / mma.sync / TMA / mbarrier)
// ---------------------------------------------------------------------------
__device__ __forceinline__ uint32_t smem_u32(const void* p) {
    uint32_t a;
    asm("{ .reg .u64 t; cvta.to.shared.u64 t, %1; cvt.u32.u64 %0, t; }"
        : "=r"(a) : "l"(p));
    return a;
}

__device__ __forceinline__ void ldsm_x4(uint32_t (&r)[4], uint32_t addr) {
    asm volatile("ldmatrix.sync.aligned.m8n8.x4.shared.b16 {%0,%1,%2,%3}, [%4];"
        : "=r"(r[0]), "=r"(r[1]), "=r"(r[2]), "=r"(r[3]) : "r"(addr));
}

__device__ __forceinline__ void mma16816(float (&d)[4], const uint32_t (&a)[4],
                                         uint32_t b0, uint32_t b1) {
    asm volatile("mma.sync.aligned.m16n8k16.row.col.f32.f16.f16.f32 "
        "{%0,%1,%2,%3}, {%4,%5,%6,%7}, {%8,%9}, {%0,%1,%2,%3};"
        : "+f"(d[0]), "+f"(d[1]), "+f"(d[2]), "+f"(d[3])
        : "r"(a[0]), "r"(a[1]), "r"(a[2]), "r"(a[3]), "r"(b0), "r"(b1));
}

#define MBAR_INIT(addr, cnt) \
    asm volatile("mbarrier.init.shared.b64 [%0], %1;" :: "r"(addr), "r"(cnt) : "memory")
#define MBAR_ARRIVE(addr) \
    asm volatile("mbarrier.arrive.shared.b64 _, [%0];" :: "r"(addr) : "memory")
#define MBAR_EXPECT_TX(addr, bytes) \
    asm volatile("mbarrier.arrive.expect_tx.shared.b64 _, [%0], %1;" \
                 :: "r"(addr), "r"(bytes) : "memory")

__device__ __forceinline__ void mbar_wait(uint32_t addr, uint32_t parity) {
    asm volatile(
        "{\n\t.reg .pred p;\n\t"
        "WAIT_%=:\n\t"
        "mbarrier.try_wait.parity.shared.b64 p, [%0], %1;\n\t"
        "@!p bra WAIT_%=;\n\t}"
        :: "r"(addr), "r"(parity) : "memory");
}

#define TMA2D(smem, map, x, y, mbar) \
    asm volatile("cp.async.bulk.tensor.2d.shared::cta.global.tile.mbarrier::complete_tx::bytes " \
                 "[%0], [%1, {%2, %3}], [%4];" \
                 :: "r"(smem), "l"(map), "r"(x), "r"(y), "r"(mbar) : "memory")

#define FENCE_ASYNC() asm volatile("fence.proxy.async.shared::cta;" ::: "memory")

// Swizzle matching CU_TENSOR_MAP_SWIZZLE_128B with 128B rows
// (r = row, ch = 16B chunk 0..7): byte_off ^ ((byte_off>>3)&0x70)
#define SWZ(r, ch) (((r) << 7) + ((((ch) ^ ((r) & 7))) << 4))

// ---------------------------------------------------------------------------
// Reductions
// ---------------------------------------------------------------------------
template <int BS>
__device__ __forceinline__ float blockReduce(float v, float* red) {
    int tid = threadIdx.x;
    red[tid] = v;
    __syncthreads();
#pragma unroll
    for (int s = BS / 2; s > 0; s >>= 1) {
        if (tid < s) red[tid] += red[tid + s];
        __syncthreads();
    }
    float out = red[0];
    __syncthreads();
    return out;
}

__device__ __forceinline__ float fastReduce256(float v, volatile float* red,
                                               volatile float* bc) {
    int lane = threadIdx.x & 31, wid = threadIdx.x >> 5;
#pragma unroll
    for (int o = 16; o > 0; o >>= 1) v += __shfl_xor_sync(0xFFFFFFFFu, v, o);
    if (lane == 0) red[wid] = v;
    __syncthreads();
    if (wid == 0) {
        float x = (lane < 8) ? red[lane] : 0.0f;
#pragma unroll
        for (int o = 4; o > 0; o >>= 1) x += __shfl_xor_sync(0xFFFFFFFFu, x, o);
        if (lane == 0) *bc = x;
    }
    __syncthreads();
    return *bc;
}

// ---------------------------------------------------------------------------
// Grid barrier: sense-reversing, self-resetting counter + monotonic gen flag.
// ---------------------------------------------------------------------------
__device__ __forceinline__ void gridSync(unsigned& gen) {
    __syncthreads();
    if (threadIdx.x == 0) {
        __threadfence();
        unsigned target = gen + 1;
        unsigned old = atomicAdd(&g_cnt, 1);
        if (old == NCTA - 1) {
            g_cnt = 0;
            __threadfence();
            g_gen = target;
        } else {
            while (g_gen != target) { __nanosleep(32); }
        }
        __threadfence();
        gen = target;
    }
    __syncthreads();
}

// ---------------------------------------------------------------------------
// Round K to fp16 (once per launch)
// ---------------------------------------------------------------------------
__global__ void k_split(const float* __restrict__ K) {
    size_t i0 = (size_t)blockIdx.x * blockDim.x + threadIdx.x;
    size_t stride = (size_t)gridDim.x * blockDim.x;
    size_t n8 = (size_t)NN * NN / 8;
    for (size_t i = i0; i < n8; i += stride) {
        float4 a = ((const float4*)K)[2 * i];
        float4 b = ((const float4*)K)[2 * i + 1];
        union { __half h[8]; uint4 u; } H;
        H.h[0] = __float2half_rn(a.x); H.h[1] = __float2half_rn(a.y);
        H.h[2] = __float2half_rn(a.z); H.h[3] = __float2half_rn(a.w);
        H.h[4] = __float2half_rn(b.x); H.h[5] = __float2half_rn(b.y);
        H.h[6] = __float2half_rn(b.z); H.h[7] = __float2half_rn(b.w);
        ((uint4*)g_Khi16)[i] = H.u;
    }
}

// ---------------------------------------------------------------------------
// Init: B = [y | Z | 0-pad]; P = fp16(B) (scale 1), R = B, X = 0
// ---------------------------------------------------------------------------
__global__ void k_init(const float* __restrict__ y, const float* __restrict__ Z) {
    int stride = gridDim.x * blockDim.x;
    for (int idx = blockIdx.x * blockDim.x + threadIdx.x; idx < MP * NN; idx += stride) {
        int col = idx >> 13;
        int row = idx & (NN - 1);
        float v = 0.0f;
        if (col == 0)        v = y[row];
        else if (col <= 100) v = Z[row * 100 + (col - 1)];
        g_Ph16[idx] = __float2half_rn(v);
        g_R[idx] = v;
        if (col == 0) g_X[row] = 0.0f;
    }
}

// ---------------------------------------------------------------------------
// Split TMA producers (single thread). F = global monotonic fill index.
// full barrier gets TWO expect_tx arrivals per phase (K part + B part).
// ---------------------------------------------------------------------------
__device__ __forceinline__ void produceK(uint32_t sb, int F, int t_in_it,
                                         int kbase, int rb,
                                         const CUtensorMap* mK, bool waitEmpty) {
    uint32_t s = (uint32_t)(F % NSTG);
    if (waitEmpty && F >= NSTG)
        mbar_wait(sb + 64 + s * 8, (uint32_t)((F / NSTG - 1) & 1));
    FENCE_ASYNC();
    uint32_t full = sb + s * 8;
    MBAR_EXPECT_TX(full, (uint32_t)A_B);
    uint32_t st = sb + 1024 + s * STAGE_SP;
    TMA2D(st, mK, kbase + t_in_it * KT, rb, full);
}

__device__ __forceinline__ void produceB(uint32_t sb, int F, int t_in_it,
                                         int kbase, const CUtensorMap* mB) {
    uint32_t s = (uint32_t)(F % NSTG);
    uint32_t full = sb + s * 8;
    MBAR_EXPECT_TX(full, (uint32_t)B_TX);
    uint32_t st = sb + 1024 + s * STAGE_SP;
    TMA2D(st + A_B, mB, kbase + t_in_it * KT, 0, full);
}

// ---------------------------------------------------------------------------
// Persistent kernel: 30 x (GEMM phase -> gridSync -> update phase -> signal)
// 128 CTAs x 256 threads (1/SM). Warp tile 64x56, double-buffered operands,
// register-resident residual R. One grid barrier per iteration; the P-ready
// dependency is a producer-side poll on the monotonic g_done counter.
// ---------------------------------------------------------------------------
__global__ void __launch_bounds__(NTHR) k_persist(
        const __grid_constant__ CUtensorMap tmK,
        const __grid_constant__ CUtensorMap tmB) {
    extern __shared__ __align__(1024) char smem[];
    uint32_t sb = smem_u32(smem);
    volatile float* red = (volatile float*)(smem + 128);   // 8 floats
    volatile float* bcp = (volatile float*)(smem + 256);

    int tid = threadIdx.x, lane = tid & 31, w = tid >> 5;
    int wm = w & 3, wn = w >> 2;          // 4 m-bands x 2 n-bands
    int bid = blockIdx.x;
    int rb = (bid & 31) * ROWB;
    int ksp = bid >> 5;
    int kbase = ksp * KCHUNK;

    // init mbarriers: full[s] count 2 (K + B expect_tx), empty[s] count NTHR
    if (tid == 0) {
#pragma unroll
        for (int s = 0; s < NSTG; s++) {
            MBAR_INIT(sb + s * 8, 2u);
            MBAR_INIT(sb + 64 + s * 8, (uint32_t)NTHR);
        }
    }
    __syncthreads();

    unsigned gen = g_gen;     // safe: read before any barrier can complete
    unsigned dbase = g_done;  // safe: no update signals before gridSync of it 0

    int rA = wm * 64 + (lane & 15);
    int rB = wn * 56 + (lane & 15);
    int chHalf = lane >> 4;

    // per-column CG state: residual R in registers (8 float4 = 32 regs),
    // scalars rs / scale uniform across the CTA
    float4 Rreg[8];
    float rs = 0.0f, csc = 1.0f;
    if (bid < MREAL) {
        const float4* R4 = (const float4*)(g_R + (size_t)bid * NN);
        float s = 0.0f;
#pragma unroll
        for (int t = 0; t < 8; t++) {
            float4 rv = R4[t * NTHR + tid];
            Rreg[t] = rv;
            s += rv.x * rv.x + rv.y * rv.y + rv.z * rv.z + rv.w * rv.w;
        }
        rs = fastReduce256(s, red, bcp);
    }
    __syncthreads();

    // prologue K fill for iteration 0 (buffers fresh -> no empty wait)
    if (tid == 0) {
#pragma unroll
        for (int s = 0; s < NSTG - 1; s++)
            produceK(sb, s, s, kbase, rb, &tmK, false);
    }

    for (int it = 0; it < PITER; it++) {
        int Fbase = it * KITERS;

        // B prologue: poll until all columns' P writes (iter it-1) landed.
        if (tid == 0) {
            unsigned target = dbase + (unsigned)it * MREAL;
            while ((int)(g_done - target) < 0) { __nanosleep(64); }
            __threadfence();
#pragma unroll
            for (int s = 0; s < NSTG - 1; s++)
                produceB(sb, Fbase + s, s, kbase, &tmB);
        }

        // ------------------------------ GEMM phase ------------------------
        float acc[4][7][4];
#pragma unroll
        for (int mi = 0; mi < 4; mi++)
#pragma unroll
            for (int nj = 0; nj < 7; nj++)
#pragma unroll
                for (int q = 0; q < 4; q++) acc[mi][nj][q] = 0.0f;

        for (int t = 0; t < KITERS; t++) {
            int F = Fbase + t;
            if (tid == 0 && t + NSTG - 1 < KITERS) {
                produceK(sb, F + NSTG - 1, t + NSTG - 1, kbase, rb, &tmK, true);
                produceB(sb, F + NSTG - 1, t + NSTG - 1, kbase, &tmB);
            }

            uint32_t s = (uint32_t)(F % NSTG);
            mbar_wait(sb + s * 8, (uint32_t)((F / NSTG) & 1));
            uint32_t st = sb + 1024 + s * STAGE_SP;

            // software-pipelined operands: prefetch kk+1 before kk's MMAs
            uint32_t ah[2][4][4], bh[2][4][4];
            {
                int ch = chHalf;
#pragma unroll
                for (int i = 0; i < 4; i++)
                    ldsm_x4(ah[0][i], st + SWZ(rA + i * 16, ch));
#pragma unroll
                for (int nb = 0; nb < 4; nb++)
                    ldsm_x4(bh[0][nb], st + A_B + SWZ(rB + nb * 16, ch));
            }
#pragma unroll
            for (int kk = 0; kk < 4; kk++) {
                int cur = kk & 1, nxt = cur ^ 1;
                if (kk < 3) {
                    int ch = (kk + 1) * 2 + chHalf;
#pragma unroll
                    for (int i = 0; i < 4; i++)
                        ldsm_x4(ah[nxt][i], st + SWZ(rA + i * 16, ch));
#pragma unroll
                    for (int nb = 0; nb < 4; nb++)
                        ldsm_x4(bh[nxt][nb], st + A_B + SWZ(rB + nb * 16, ch));
                }
#pragma unroll
                for (int mi = 0; mi < 4; mi++)
#pragma unroll
                    for (int nj = 0; nj < 7; nj++) {
                        int g = nj >> 1, sel = nj & 1;
                        mma16816(acc[mi][nj], ah[cur][mi],
                                 bh[cur][g][sel], bh[cur][g][sel + 2]);
                    }
            }
            MBAR_ARRIVE(sb + 64 + s * 8);
        }

        // cross-iteration K prefetch: next iter's first stages (K only)
        if (tid == 0 && it + 1 < PITER) {
            int Fn = (it + 1) * KITERS;
#pragma unroll
            for (int s = 0; s < NSTG - 1; s++)
                produceK(sb, Fn + s, s, kbase, rb, &tmK, true);
        }

        {   // epilogue: scatter fp32 accumulators to Vpart (col-major)
            float* vp = g_Vpart + (size_t)ksp * MP * NN;
            int row0 = rb + wm * 64 + (lane >> 2);
            int col0 = wn * 56 + (lane & 3) * 2;
#pragma unroll
            for (int mi = 0; mi < 4; mi++)
#pragma unroll
                for (int nj = 0; nj < 7; nj++) {
                    int r_ = row0 + mi * 16;
                    int c_ = col0 + nj * 8;
                    vp[(size_t)c_ * NN + r_]           = acc[mi][nj][0];
                    vp[(size_t)(c_ + 1) * NN + r_]     = acc[mi][nj][1];
                    vp[(size_t)c_ * NN + r_ + 8]       = acc[mi][nj][2];
                    vp[(size_t)(c_ + 1) * NN + r_ + 8] = acc[mi][nj][3];
                }
        }

        gridSync(gen);   // Vpart complete before update reads it

        // ------------------------------ update phase ----------------------
        if (bid < MREAL) {
            int j = bid;
            const float4* V0 = (const float4*)g_Vpart + (size_t)j * NN / 4;
            const size_t PL = (size_t)MP * NN / 4;
            const uint2* Ph2 = (const uint2*)(g_Ph16 + (size_t)j * NN);

            float4 p[8], v[8];
            float pv = 0.0f;
#pragma unroll
            for (int t = 0; t < 8; t++) {
                int i4 = t * NTHR + tid;
                float4 a = __ldcg(V0 + i4);
                float4 b = __ldcg(V0 + PL + i4);
                float4 d2 = __ldcg(V0 + 2 * PL + i4);
                float4 e2 = __ldcg(V0 + 3 * PL + i4);
                float4 s = make_float4(a.x + b.x + d2.x + e2.x,
                                       a.y + b.y + d2.y + e2.y,
                                       a.z + b.z + d2.z + e2.z,
                                       a.w + b.w + d2.w + e2.w);
                v[t] = s;
                uint2 hu = Ph2[i4];
                __half2 h0 = *(__half2*)&hu.x, h1 = *(__half2*)&hu.y;
                float2 f0 = __half22float2(h0), f1 = __half22float2(h1);
                float4 pp = make_float4(f0.x, f0.y, f1.x, f1.y);
                p[t] = pp;
                pv += pp.x * s.x + pp.y * s.y + pp.z * s.z + pp.w * s.w;
            }
            pv = fastReduce256(pv, red, bcp);      // = c^2 * (P.V)
            float alpha = rs * csc * csc / pv;
            float aoc = alpha / csc;

            float rr = 0.0f;
#pragma unroll
            for (int t = 0; t < 8; t++) {
                float4 rv = Rreg[t];
                rv.x -= aoc * v[t].x; rv.y -= aoc * v[t].y;
                rv.z -= aoc * v[t].z; rv.w -= aoc * v[t].w;
                Rreg[t] = rv;
                rr += rv.x * rv.x + rv.y * rv.y + rv.z * rv.z + rv.w * rv.w;
            }
            if (j == 0) {
                float4* X4 = (float4*)g_X;
#pragma unroll
                for (int t = 0; t < 8; t++) {
                    int i4 = t * NTHR + tid;
                    float4 x = X4[i4];
                    x.x += aoc * p[t].x; x.y += aoc * p[t].y;
                    x.z += aoc * p[t].z; x.w += aoc * p[t].w;
                    X4[i4] = x;
                }
            }
            rr = fastReduce256(rr, red, bcp);
            float beta = rr / rs;
            float c2 = exp2f(-rintf(0.5f * log2f(rr * (1.0f / (float)NN))));
            if (tid == 0) {
                g_alpha[it * MP + j] = alpha;
                g_beta[it * MP + j]  = beta;
            }
            float boc = beta / csc;

            uint2* Phw = (uint2*)(g_Ph16 + (size_t)j * NN);
#pragma unroll
            for (int t = 0; t < 8; t++) {
                int i4 = t * NTHR + tid;
                float pn[4] = {
                    Rreg[t].x + boc * p[t].x, Rreg[t].y + boc * p[t].y,
                    Rreg[t].z + boc * p[t].z, Rreg[t].w + boc * p[t].w };
                __half2 t0 = __floats2half2_rn(c2 * pn[0], c2 * pn[1]);
                __half2 t1 = __floats2half2_rn(c2 * pn[2], c2 * pn[3]);
                uint2 hu;
                hu.x = *(uint32_t*)&t0; hu.y = *(uint32_t*)&t1;
                Phw[i4] = hu;
            }
            rs = rr;
            csc = c2;

            // signal: this column's P is published
            __syncthreads();
            if (tid == 0) {
                __threadfence();
                atomicAdd((unsigned*)&g_done, 1u);
            }
        }
    }
}

// ---------------------------------------------------------------------------
// SLQ logdet (TQLI on 30x30 tridiagonal, first-row eigenvector weights)
// ---------------------------------------------------------------------------
__device__ void tqli30(double* d, double* e, double* z) {
    const int n = PITER;
    for (int l = 0; l < n; l++) {
        int iter = 0;
        int m;
        do {
            for (m = l; m < n - 1; m++) {
                double dd = fabs(d[m]) + fabs(d[m + 1]);
                if (fabs(e[m]) <= 2.3e-16 * dd) break;
            }
            if (m != l) {
                if (iter++ == 64) break;
                double g = (d[l + 1] - d[l]) / (2.0 * e[l]);
                double rr = sqrt(g * g + 1.0);
                double sg = (g >= 0.0) ? rr : -rr;
                g = d[m] - d[l] + e[l] / (g + sg);
                double s = 1.0, cc = 1.0, p = 0.0;
                bool under = false;
                for (int i = m - 1; i >= l; i--) {
                    double f = s * e[i];
                    double b = cc * e[i];
                    double rq = sqrt(f * f + g * g);
                    e[i + 1] = rq;
                    if (rq == 0.0) {
                        d[i + 1] -= p;
                        e[m] = 0.0;
                        under = true;
                        break;
                    }
                    s = f / rq; cc = g / rq;
                    g = d[i + 1] - p;
                    rq = (d[i] - g) * s + 2.0 * cc * b;
                    p = s * rq;
                    d[i + 1] = g + p;
                    g = cc * rq - b;
                    double zi = z[i], zi1 = z[i + 1];
                    z[i + 1] = s * zi + cc * zi1;
                    z[i]     = cc * zi - s * zi1;
                }
                if (under) continue;
                d[l] -= p;
                e[l] = g;
                e[m] = 0.0;
            }
        } while (m != l);
    }
}

__global__ void k_logdet() {
    __shared__ double qsum[128];
    int tid = threadIdx.x;
    double quad = 0.0;
    if (tid < 100) {
        int j = tid + 1;
        double d[PITER], e[PITER], z[PITER];
        double pa = 1.0, pb = 0.0;
        for (int k = 0; k < PITER; k++) {
            double a = (double)g_alpha[k * MP + j];
            double b = (double)g_beta[k * MP + j];
            d[k] = 1.0 / a + ((k > 0) ? pb / pa : 0.0);
            e[k] = (k < PITER - 1) ? sqrt(b) / a : 0.0;
            z[k] = (k == 0) ? 1.0 : 0.0;
            pa = a; pb = b;
        }
        tqli30(d, e, z);
        for (int k = 0; k < PITER; k++) {
            double lam = d[k] < 1e-12 ? 1e-12 : d[k];
            quad += z[k] * z[k] * log(lam);
        }
    }
    qsum[tid] = quad;
    __syncthreads();
    if (tid == 0) {
        double s = 0.0;
        for (int i = 0; i < 100; i++) s += qsum[i];
        g_logdet = (float)((double)NN * s / 100.0);
    }
}

__global__ void k_final(const float* __restrict__ y, float* __restrict__ out) {
    __shared__ float red[256];
    float s = 0.0f;
    for (int i = threadIdx.x; i < NN; i += 256) s += y[i] * g_X[i];
    s = blockReduce<256>(s, red);
    if (threadIdx.x == 0) {
        const double LOG2PI = 1.8378770664093454836;
        double r = -0.5 * (double)s - 0.5 * (double)g_logdet - 0.5 * (double)NN * LOG2PI;
        out[0] = (float)r;
    }
}

// ---------------------------------------------------------------------------
// Launch: build TensorMaps via driver entry point (cudart-only), then chain.
// ---------------------------------------------------------------------------
typedef CUresult (*PFN_encodeTiled)(
    CUtensorMap*, CUtensorMapDataType, cuuint32_t, void*,
    const cuuint64_t*, const cuuint64_t*, const cuuint32_t*, const cuuint32_t*,
    CUtensorMapInterleave, CUtensorMapSwizzle, CUtensorMapL2promotion,
    CUtensorMapFloatOOBfill);

extern "C" void kernel_launch(void* const* d_in, const int* in_sizes, int n_in,
                              void* d_out, int out_size) {
    const float* K = (const float*)d_in[0];
    const float* y = (const float*)d_in[1];
    const float* Z = (const float*)d_in[2];
    float* out = (float*)d_out;

    // resolve cuTensorMapEncodeTiled through cudart (no -lcuda needed)
    void* fn = nullptr;
    cudaDriverEntryPointQueryResult qres;
    cudaGetDriverEntryPointByVersion("cuTensorMapEncodeTiled", &fn, 12000,
                                     cudaEnableDefault, &qres);
    PFN_encodeTiled enc = (PFN_encodeTiled)fn;

    void *pK = nullptr, *pPh = nullptr;
    cudaGetSymbolAddress(&pK, g_Khi16);
    cudaGetSymbolAddress(&pPh, g_Ph16);

    CUtensorMap tmK, tmB;
    {
        cuuint64_t dims[2] = {NN, NN};
        cuuint64_t strides[1] = {NN * 2};
        cuuint32_t box[2] = {64, 256};
        cuuint32_t es[2] = {1, 1};
        enc(&tmK, CU_TENSOR_MAP_DATA_TYPE_FLOAT16, 2, pK, dims, strides, box, es,
            CU_TENSOR_MAP_INTERLEAVE_NONE, CU_TENSOR_MAP_SWIZZLE_128B,
            CU_TENSOR_MAP_L2_PROMOTION_L2_128B, CU_TENSOR_MAP_FLOAT_OOB_FILL_NONE);
    }
    {
        cuuint64_t dims[2] = {NN, MP};
        cuuint64_t strides[1] = {NN * 2};
        cuuint32_t box[2] = {64, NCOLS};
        cuuint32_t es[2] = {1, 1};
        enc(&tmB, CU_TENSOR_MAP_DATA_TYPE_FLOAT16, 2, pPh, dims, strides, box, es,
            CU_TENSOR_MAP_INTERLEAVE_NONE, CU_TENSOR_MAP_SWIZZLE_128B,
            CU_TENSOR_MAP_L2_PROMOTION_L2_128B, CU_TENSOR_MAP_FLOAT_OOB_FILL_NONE);
    }

    cudaFuncSetAttribute(k_persist, cudaFuncAttributeMaxDynamicSharedMemorySize,
                         SMEM_DYN);

    k_split<<<4096, 256>>>(K);
    k_init<<<512, 256>>>(y, Z);
    k_persist<<<NCTA, NTHR, SMEM_DYN>>>(tmK, tmB);
    k_logdet<<<1, 128>>>();
    k_final<<<1, 256>>>(y, out);
}